// round 2
// baseline (speedup 1.0000x reference)
#include <cuda_runtime.h>

#define NTHREADS 256
#define PTS_PER_BLOCK (NTHREADS / 4)

// Per-plane sampling parameters for one lane of a 4-lane quad.
struct PlaneSetup {
    int   base;   // float4 index of this lane's TOP-row load
    float ap;     // x-weight for this lane's column (p = lane>>1)
    float b0, b1; // y-weights for top/bottom rows
};

__device__ __forceinline__ PlaneSetup plane_setup(float u, float v, int s, int p)
{
    // unnormalize (align_corners=False) + border clamp, matching reference op order
    float x = ((u + 1.0f) * 512.0f - 1.0f) * 0.5f;
    float y = ((v + 1.0f) * 512.0f - 1.0f) * 0.5f;
    x = fminf(fmaxf(x, 0.0f), 511.0f);
    y = fminf(fmaxf(y, 0.0f), 511.0f);

    float x0f = floorf(x);
    float y0f = floorf(y);
    float wx = x - x0f;
    float wy = y - y0f;
    int x0 = (int)x0f;
    int y0 = (int)y0f;

    // Load columns [xb, xb+1] and rows [yb, yb+1]; fold clamping into weights.
    // When x0==511: wx==0 and v01==v00 -> weight of column xb+1 (=511) is 1.
    int xb = min(x0, 510);
    int yb = min(y0, 510);

    PlaneSetup ps;
    float a1 = (x0 == 511) ? 1.0f : wx;   // weight of column xb+1
    ps.ap = p ? a1 : (1.0f - a1);         // this lane's column weight
    ps.b1 = (y0 == 511) ? 1.0f : wy;      // weight of row yb+1
    ps.b0 = 1.0f - ps.b1;
    // texel (yb, xb) starts at float4 index ((yb*512+xb)*2); lane s covers 16B slot s
    ps.base = (((yb << 9) + xb) << 1) + s;
    return ps;
}

// Accumulate this lane's partial matvec contribution for one plane.
// top/bot: this lane's float4 (ranks half*4..half*4+3 of texel column p).
__device__ __forceinline__ void accum_plane(
    const PlaneSetup& ps, float4 top, float4 bot,
    const float* __restrict__ Wsm, int wbase, int half,
    float4& acc0, float4& acc1)
{
    // y-lerp then x-weight: pf[r] = ap * (b0*top[r] + b1*bot[r])
    float pf0 = ps.ap * (ps.b0 * top.x + ps.b1 * bot.x);
    float pf1 = ps.ap * (ps.b0 * top.y + ps.b1 * bot.y);
    float pf2 = ps.ap * (ps.b0 * top.z + ps.b1 * bot.z);
    float pf3 = ps.ap * (ps.b0 * top.w + ps.b1 * bot.w);

    const float4* wr = reinterpret_cast<const float4*>(Wsm + ((wbase + half * 4) << 3));
    #pragma unroll
    for (int r = 0; r < 4; r++) {
        float sc = (r == 0) ? pf0 : (r == 1) ? pf1 : (r == 2) ? pf2 : pf3;
        float4 w0 = wr[2 * r + 0];
        float4 w1 = wr[2 * r + 1];
        acc0.x += sc * w0.x;  acc0.y += sc * w0.y;  acc0.z += sc * w0.z;  acc0.w += sc * w0.w;
        acc1.x += sc * w1.x;  acc1.y += sc * w1.y;  acc1.z += sc * w1.z;  acc1.w += sc * w1.w;
    }
}

__global__ void __launch_bounds__(NTHREADS)
geo_encoder_kernel(
    const float*  __restrict__ coords,   // [N,3]
    const float4* __restrict__ pxy,
    const float4* __restrict__ pxz,
    const float4* __restrict__ pyz,
    const float*  __restrict__ Wp,       // [8,24]
    const float*  __restrict__ bp,       // [8]
    float*        __restrict__ out,      // [N,8]
    int n)
{
    __shared__ float Wsm[192];   // transposed: Wsm[k*8+j] = Wp[j*24+k]
    __shared__ float bsm[8];

    const int t = threadIdx.x;
    if (t < 192) Wsm[t] = Wp[(t & 7) * 24 + (t >> 3)];
    if (t < 8)   bsm[t] = bp[t];
    __syncthreads();

    const int s    = t & 3;        // sub-lane within quad
    const int p    = s >> 1;       // x-column (0 or 1) this lane loads
    const int half = s & 1;        // rank half (float4 index within texel)
    const int i    = blockIdx.x * PTS_PER_BLOCK + (t >> 2);
    if (i >= n) return;

    // all 4 lanes of a quad read the same coords (L1 broadcast)
    float cx = __ldg(coords + 3 * i + 0);
    float cy = __ldg(coords + 3 * i + 1);
    float cz = __ldg(coords + 3 * i + 2);
    cx = fminf(fmaxf(cx, -1.0f), 1.0f);
    cy = fminf(fmaxf(cy, -1.0f), 1.0f);
    cz = fminf(fmaxf(cz, -1.0f), 1.0f);

    // compute all addresses first, then issue all 6 gathers for max MLP
    PlaneSetup sxy = plane_setup(cx, cy, s, p);
    PlaneSetup sxz = plane_setup(cx, cz, s, p);
    PlaneSetup syz = plane_setup(cy, cz, s, p);

    const float4 t_xy = __ldg(pxy + sxy.base);
    const float4 b_xy = __ldg(pxy + sxy.base + 1024);   // +1 row = 512 texels = 1024 float4
    const float4 t_xz = __ldg(pxz + sxz.base);
    const float4 b_xz = __ldg(pxz + sxz.base + 1024);
    const float4 t_yz = __ldg(pyz + syz.base);
    const float4 b_yz = __ldg(pyz + syz.base + 1024);

    float4 acc0 = make_float4(0.f, 0.f, 0.f, 0.f);
    float4 acc1 = make_float4(0.f, 0.f, 0.f, 0.f);

    accum_plane(sxy, t_xy, b_xy, Wsm,  0, half, acc0, acc1);
    accum_plane(sxz, t_xz, b_xz, Wsm,  8, half, acc0, acc1);
    accum_plane(syz, t_yz, b_yz, Wsm, 16, half, acc0, acc1);

    // butterfly-reduce the quad's partial sums (lanes i, i^1, i^2, i^3)
    #pragma unroll
    for (int m = 1; m < 4; m <<= 1) {
        acc0.x += __shfl_xor_sync(0xffffffffu, acc0.x, m);
        acc0.y += __shfl_xor_sync(0xffffffffu, acc0.y, m);
        acc0.z += __shfl_xor_sync(0xffffffffu, acc0.z, m);
        acc0.w += __shfl_xor_sync(0xffffffffu, acc0.w, m);
        acc1.x += __shfl_xor_sync(0xffffffffu, acc1.x, m);
        acc1.y += __shfl_xor_sync(0xffffffffu, acc1.y, m);
        acc1.z += __shfl_xor_sync(0xffffffffu, acc1.z, m);
        acc1.w += __shfl_xor_sync(0xffffffffu, acc1.w, m);
    }

    // lanes 0 and 1 of each quad store the two output float4s (coalesced 256B/warp)
    if (s < 2) {
        float4 v = (s == 0) ? acc0 : acc1;
        const float* bb = bsm + (s << 2);
        v.x = fminf(fmaxf(v.x + bb[0], -10.0f), 10.0f);
        v.y = fminf(fmaxf(v.y + bb[1], -10.0f), 10.0f);
        v.z = fminf(fmaxf(v.z + bb[2], -10.0f), 10.0f);
        v.w = fminf(fmaxf(v.w + bb[3], -10.0f), 10.0f);
        reinterpret_cast<float4*>(out)[(i << 1) + s] = v;
    }
}

extern "C" void kernel_launch(void* const* d_in, const int* in_sizes, int n_in,
                              void* d_out, int out_size)
{
    const float*  coords = (const float*)d_in[0];
    const float4* pxy    = (const float4*)d_in[1];
    const float4* pxz    = (const float4*)d_in[2];
    const float4* pyz    = (const float4*)d_in[3];
    const float*  Wp     = (const float*)d_in[4];
    const float*  bp     = (const float*)d_in[5];
    float*        out    = (float*)d_out;

    const int n = in_sizes[0] / 3;
    const int blocks = (n + PTS_PER_BLOCK - 1) / PTS_PER_BLOCK;
    geo_encoder_kernel<<<blocks, NTHREADS>>>(coords, pxy, pxz, pyz, Wp, bp, out, n);
}

// round 3
// speedup vs baseline: 1.5348x; 1.5348x over previous
#include <cuda_runtime.h>

#define NTHREADS 256
#define NBLOCKS  296          // 148 SMs x 2 resident blocks (persistent grid)

struct PS { int base; float ap, b0, b1; };

// Per-plane sampling params for one lane (sub-lane s, column p=s>>1).
__device__ __forceinline__ PS plane_setup(float u, float v, int s, int p)
{
    // unnormalize (align_corners=False) + border clamp, reference op order
    float x = ((u + 1.0f) * 512.0f - 1.0f) * 0.5f;
    float y = ((v + 1.0f) * 512.0f - 1.0f) * 0.5f;
    x = fminf(fmaxf(x, 0.0f), 511.0f);
    y = fminf(fmaxf(y, 0.0f), 511.0f);

    float x0f = floorf(x);
    float y0f = floorf(y);
    float wx = x - x0f;
    float wy = y - y0f;
    int x0 = (int)x0f;
    int y0 = (int)y0f;

    int xb = min(x0, 510);
    int yb = min(y0, 510);

    PS ps;
    float a1 = (x0 == 511) ? 1.0f : wx;   // weight of column xb+1 (wx==0 there -> exact)
    ps.ap = p ? a1 : (1.0f - a1);
    ps.b1 = (y0 == 511) ? 1.0f : wy;
    ps.b0 = 1.0f - ps.b1;
    ps.base = (((yb << 9) + xb) << 1) + s;  // float4 index; slots: [x0h0 x0h1 x1h0 x1h1]
    return ps;
}

__global__ void __launch_bounds__(NTHREADS, 2)
geo_encoder_kernel(
    const float*  __restrict__ coords,   // [N,3]
    const float4* __restrict__ pxy,
    const float4* __restrict__ pxz,
    const float4* __restrict__ pyz,
    const float*  __restrict__ Wp,       // [8,24]
    const float*  __restrict__ bp,       // [8]
    float*        __restrict__ out,      // [N,8]
    int n)
{
    const int t   = threadIdx.x;
    const int s   = t & 3;       // sub-lane in quad
    const int h   = s & 1;       // rank half this lane loads (float4 within texel)
    const int p   = s >> 1;      // x-column this lane loads
    const int grp = s >> 1;      // output group: lanes {0,1}->outs 0..3, {2,3}->outs 4..7

    // ---- W slice into registers (once per thread, amortized over the loop) ----
    // Wreg[j*12 + q*4 + r] = W[4*grp+j][q*8 + h*4 + r]   (q=plane, r=rank-in-half)
    float Wreg[48];
    float bias[4];
    const int row0 = 4 * grp;
    #pragma unroll
    for (int j = 0; j < 4; j++) {
        bias[j] = __ldg(bp + row0 + j);
        #pragma unroll
        for (int q = 0; q < 3; q++)
            #pragma unroll
            for (int r = 0; r < 4; r++)
                Wreg[j * 12 + q * 4 + r] = __ldg(Wp + (row0 + j) * 24 + q * 8 + h * 4 + r);
    }

    const int quad   = (blockIdx.x * NTHREADS + t) >> 2;
    const int nquads = (NBLOCKS * NTHREADS) >> 2;
    const int niter  = (n + nquads - 1) / nquads;   // uniform across all lanes

    for (int k = 0; k < niter; k++) {
        const int  i   = quad + k * nquads;
        const bool act = (i < n);
        const int  ie  = act ? i : 0;

        float cx = __ldg(coords + 3 * ie + 0);
        float cy = __ldg(coords + 3 * ie + 1);
        float cz = __ldg(coords + 3 * ie + 2);
        cx = fminf(fmaxf(cx, -1.0f), 1.0f);
        cy = fminf(fmaxf(cy, -1.0f), 1.0f);
        cz = fminf(fmaxf(cz, -1.0f), 1.0f);

        PS a = plane_setup(cx, cy, s, p);
        PS b = plane_setup(cx, cz, s, p);
        PS c = plane_setup(cy, cz, s, p);

        // 6 gathers, all independent (max MLP). +1024 float4 = next row.
        const float4 ta = __ldg(pxy + a.base);
        const float4 ba = __ldg(pxy + a.base + 1024);
        const float4 tb = __ldg(pxz + b.base);
        const float4 bb = __ldg(pxz + b.base + 1024);
        const float4 tc = __ldg(pyz + c.base);
        const float4 bc = __ldg(pyz + c.base + 1024);

        // partial features: column-weighted y-lerp, 4 ranks per plane
        float pf[12];
        pf[0]  = a.ap * (a.b0 * ta.x + a.b1 * ba.x);
        pf[1]  = a.ap * (a.b0 * ta.y + a.b1 * ba.y);
        pf[2]  = a.ap * (a.b0 * ta.z + a.b1 * ba.z);
        pf[3]  = a.ap * (a.b0 * ta.w + a.b1 * ba.w);
        pf[4]  = b.ap * (b.b0 * tb.x + b.b1 * bb.x);
        pf[5]  = b.ap * (b.b0 * tb.y + b.b1 * bb.y);
        pf[6]  = b.ap * (b.b0 * tb.z + b.b1 * bb.z);
        pf[7]  = b.ap * (b.b0 * tb.w + b.b1 * bb.w);
        pf[8]  = c.ap * (c.b0 * tc.x + c.b1 * bc.x);
        pf[9]  = c.ap * (c.b0 * tc.y + c.b1 * bc.y);
        pf[10] = c.ap * (c.b0 * tc.z + c.b1 * bc.z);
        pf[11] = c.ap * (c.b0 * tc.w + c.b1 * bc.w);

        // reduce over x-columns (xor flips bit1 = p, same h): g = full features of half h
        float g[12];
        #pragma unroll
        for (int q = 0; q < 12; q++)
            g[q] = pf[q] + __shfl_xor_sync(0xffffffffu, pf[q], 2);

        // register matvec: partials of outputs 4*grp..4*grp+3 over this half's features
        float o0 = 0.f, o1 = 0.f, o2 = 0.f, o3 = 0.f;
        #pragma unroll
        for (int q = 0; q < 12; q++) {
            o0 += Wreg[q]      * g[q];
            o1 += Wreg[12 + q] * g[q];
            o2 += Wreg[24 + q] * g[q];
            o3 += Wreg[36 + q] * g[q];
        }

        // combine the two halves (xor flips bit0 = h, same grp)
        o0 += __shfl_xor_sync(0xffffffffu, o0, 1);
        o1 += __shfl_xor_sync(0xffffffffu, o1, 1);
        o2 += __shfl_xor_sync(0xffffffffu, o2, 1);
        o3 += __shfl_xor_sync(0xffffffffu, o3, 1);

        if (act && h == 0) {
            float4 v;
            v.x = fminf(fmaxf(o0 + bias[0], -10.0f), 10.0f);
            v.y = fminf(fmaxf(o1 + bias[1], -10.0f), 10.0f);
            v.z = fminf(fmaxf(o2 + bias[2], -10.0f), 10.0f);
            v.w = fminf(fmaxf(o3 + bias[3], -10.0f), 10.0f);
            reinterpret_cast<float4*>(out)[(i << 1) + grp] = v;
        }
    }
}

extern "C" void kernel_launch(void* const* d_in, const int* in_sizes, int n_in,
                              void* d_out, int out_size)
{
    const float*  coords = (const float*)d_in[0];
    const float4* pxy    = (const float4*)d_in[1];
    const float4* pxz    = (const float4*)d_in[2];
    const float4* pyz    = (const float4*)d_in[3];
    const float*  Wp     = (const float*)d_in[4];
    const float*  bp     = (const float*)d_in[5];
    float*        out    = (float*)d_out;

    const int n = in_sizes[0] / 3;
    geo_encoder_kernel<<<NBLOCKS, NTHREADS>>>(coords, pxy, pxz, pyz, Wp, bp, out, n);
}

// round 4
// speedup vs baseline: 1.5907x; 1.0364x over previous
#include <cuda_runtime.h>

#define NTHREADS 256
#define NBLOCKS  296          // 148 SMs x 2 resident blocks (persistent grid)

struct PS { int base; float ap, b0, b1; };

// Per-plane sampling params for one lane (sub-lane s, column p=s>>1).
__device__ __forceinline__ PS plane_setup(float u, float v, int s, int p)
{
    // unnormalize (align_corners=False) + border clamp, reference op order
    float x = ((u + 1.0f) * 512.0f - 1.0f) * 0.5f;
    float y = ((v + 1.0f) * 512.0f - 1.0f) * 0.5f;
    x = fminf(fmaxf(x, 0.0f), 511.0f);
    y = fminf(fmaxf(y, 0.0f), 511.0f);

    float x0f = floorf(x);
    float y0f = floorf(y);
    float wx = x - x0f;
    float wy = y - y0f;
    int x0 = (int)x0f;
    int y0 = (int)y0f;

    int xb = min(x0, 510);
    int yb = min(y0, 510);

    PS ps;
    float a1 = (x0 == 511) ? 1.0f : wx;   // weight of column xb+1 (wx==0 there -> exact)
    ps.ap = p ? a1 : (1.0f - a1);
    ps.b1 = (y0 == 511) ? 1.0f : wy;
    ps.b0 = 1.0f - ps.b1;
    ps.base = (((yb << 9) + xb) << 1) + s;  // float4 index; slots: [x0h0 x0h1 x1h0 x1h1]
    return ps;
}

// y-lerp * column-weight for one plane's 4 ranks
__device__ __forceinline__ void pf4(const PS& ps, float4 tp, float4 bt, float* pf)
{
    pf[0] = ps.ap * (ps.b0 * tp.x + ps.b1 * bt.x);
    pf[1] = ps.ap * (ps.b0 * tp.y + ps.b1 * bt.y);
    pf[2] = ps.ap * (ps.b0 * tp.z + ps.b1 * bt.z);
    pf[3] = ps.ap * (ps.b0 * tp.w + ps.b1 * bt.w);
}

__global__ void __launch_bounds__(NTHREADS, 2)
geo_encoder_kernel(
    const float*  __restrict__ coords,   // [N,3]
    const float4* __restrict__ pxy,
    const float4* __restrict__ pxz,
    const float4* __restrict__ pyz,
    const float*  __restrict__ Wp,       // [8,24]
    const float*  __restrict__ bp,       // [8]
    float*        __restrict__ out,      // [N,8]
    int n)
{
    const int t   = threadIdx.x;
    const int s   = t & 3;       // sub-lane in quad
    const int h   = s & 1;       // rank half this lane loads (float4 within texel)
    const int p   = s >> 1;      // x-column this lane loads; also output group
    const int grp = s >> 1;

    // W slice in registers: Wreg[j*12 + q*4 + r] = W[4*grp+j][q*8 + h*4 + r]
    float Wreg[48];
    float bias[4];
    const int row0 = 4 * grp;
    #pragma unroll
    for (int j = 0; j < 4; j++) {
        bias[j] = __ldg(bp + row0 + j);
        #pragma unroll
        for (int q = 0; q < 3; q++)
            #pragma unroll
            for (int r = 0; r < 4; r++)
                Wreg[j * 12 + q * 4 + r] = __ldg(Wp + (row0 + j) * 24 + q * 8 + h * 4 + r);
    }

    const int quad   = (blockIdx.x * NTHREADS + t) >> 2;
    const int nquads = (NBLOCKS * NTHREADS) >> 2;
    const int niter  = (n + nquads - 1) / nquads;

    for (int k = 0; k < niter; k += 2) {
        const int  i0   = quad + k * nquads;
        const int  i1   = i0 + nquads;
        const bool act0 = (i0 < n);
        const bool act1 = (i1 < n);
        const int  e0   = act0 ? i0 : 0;
        const int  e1   = act1 ? i1 : 0;

        // ---- coords for both points ----
        float cx0 = __ldg(coords + 3 * e0 + 0);
        float cy0 = __ldg(coords + 3 * e0 + 1);
        float cz0 = __ldg(coords + 3 * e0 + 2);
        float cx1 = __ldg(coords + 3 * e1 + 0);
        float cy1 = __ldg(coords + 3 * e1 + 1);
        float cz1 = __ldg(coords + 3 * e1 + 2);
        cx0 = fminf(fmaxf(cx0, -1.0f), 1.0f);
        cy0 = fminf(fmaxf(cy0, -1.0f), 1.0f);
        cz0 = fminf(fmaxf(cz0, -1.0f), 1.0f);
        cx1 = fminf(fmaxf(cx1, -1.0f), 1.0f);
        cy1 = fminf(fmaxf(cy1, -1.0f), 1.0f);
        cz1 = fminf(fmaxf(cz1, -1.0f), 1.0f);

        PS a0 = plane_setup(cx0, cy0, s, p);
        PS b0 = plane_setup(cx0, cz0, s, p);
        PS c0 = plane_setup(cy0, cz0, s, p);
        PS a1 = plane_setup(cx1, cy1, s, p);
        PS b1 = plane_setup(cx1, cz1, s, p);
        PS c1 = plane_setup(cy1, cz1, s, p);

        // ---- 12 independent gathers, front-batched for MLP ----
        const float4 ta0 = __ldg(pxy + a0.base);
        const float4 ba0 = __ldg(pxy + a0.base + 1024);
        const float4 tb0 = __ldg(pxz + b0.base);
        const float4 bb0 = __ldg(pxz + b0.base + 1024);
        const float4 tc0 = __ldg(pyz + c0.base);
        const float4 bc0 = __ldg(pyz + c0.base + 1024);
        const float4 ta1 = __ldg(pxy + a1.base);
        const float4 ba1 = __ldg(pxy + a1.base + 1024);
        const float4 tb1 = __ldg(pxz + b1.base);
        const float4 bb1 = __ldg(pxz + b1.base + 1024);
        const float4 tc1 = __ldg(pyz + c1.base);
        const float4 bc1 = __ldg(pyz + c1.base + 1024);

        // ---- point 0 ----
        {
            float pf[12];
            pf4(a0, ta0, ba0, pf + 0);
            pf4(b0, tb0, bb0, pf + 4);
            pf4(c0, tc0, bc0, pf + 8);

            float g[12];
            #pragma unroll
            for (int q = 0; q < 12; q++)
                g[q] = pf[q] + __shfl_xor_sync(0xffffffffu, pf[q], 2);

            float o0 = 0.f, o1 = 0.f, o2 = 0.f, o3 = 0.f;
            #pragma unroll
            for (int q = 0; q < 12; q++) {
                o0 += Wreg[q]      * g[q];
                o1 += Wreg[12 + q] * g[q];
                o2 += Wreg[24 + q] * g[q];
                o3 += Wreg[36 + q] * g[q];
            }
            o0 += __shfl_xor_sync(0xffffffffu, o0, 1);
            o1 += __shfl_xor_sync(0xffffffffu, o1, 1);
            o2 += __shfl_xor_sync(0xffffffffu, o2, 1);
            o3 += __shfl_xor_sync(0xffffffffu, o3, 1);

            if (act0 && h == 0) {
                float4 v;
                v.x = fminf(fmaxf(o0 + bias[0], -10.0f), 10.0f);
                v.y = fminf(fmaxf(o1 + bias[1], -10.0f), 10.0f);
                v.z = fminf(fmaxf(o2 + bias[2], -10.0f), 10.0f);
                v.w = fminf(fmaxf(o3 + bias[3], -10.0f), 10.0f);
                reinterpret_cast<float4*>(out)[(i0 << 1) + grp] = v;
            }
        }

        // ---- point 1 ----
        {
            float pf[12];
            pf4(a1, ta1, ba1, pf + 0);
            pf4(b1, tb1, bb1, pf + 4);
            pf4(c1, tc1, bc1, pf + 8);

            float g[12];
            #pragma unroll
            for (int q = 0; q < 12; q++)
                g[q] = pf[q] + __shfl_xor_sync(0xffffffffu, pf[q], 2);

            float o0 = 0.f, o1 = 0.f, o2 = 0.f, o3 = 0.f;
            #pragma unroll
            for (int q = 0; q < 12; q++) {
                o0 += Wreg[q]      * g[q];
                o1 += Wreg[12 + q] * g[q];
                o2 += Wreg[24 + q] * g[q];
                o3 += Wreg[36 + q] * g[q];
            }
            o0 += __shfl_xor_sync(0xffffffffu, o0, 1);
            o1 += __shfl_xor_sync(0xffffffffu, o1, 1);
            o2 += __shfl_xor_sync(0xffffffffu, o2, 1);
            o3 += __shfl_xor_sync(0xffffffffu, o3, 1);

            if (act1 && h == 0) {
                float4 v;
                v.x = fminf(fmaxf(o0 + bias[0], -10.0f), 10.0f);
                v.y = fminf(fmaxf(o1 + bias[1], -10.0f), 10.0f);
                v.z = fminf(fmaxf(o2 + bias[2], -10.0f), 10.0f);
                v.w = fminf(fmaxf(o3 + bias[3], -10.0f), 10.0f);
                reinterpret_cast<float4*>(out)[(i1 << 1) + grp] = v;
            }
        }
    }
}

extern "C" void kernel_launch(void* const* d_in, const int* in_sizes, int n_in,
                              void* d_out, int out_size)
{
    const float*  coords = (const float*)d_in[0];
    const float4* pxy    = (const float4*)d_in[1];
    const float4* pxz    = (const float4*)d_in[2];
    const float4* pyz    = (const float4*)d_in[3];
    const float*  Wp     = (const float*)d_in[4];
    const float*  bp     = (const float*)d_in[5];
    float*        out    = (float*)d_out;

    const int n = in_sizes[0] / 3;
    geo_encoder_kernel<<<NBLOCKS, NTHREADS>>>(coords, pxy, pxz, pyz, Wp, bp, out, n);
}

// round 5
// speedup vs baseline: 1.6635x; 1.0458x over previous
#include <cuda_runtime.h>

#define NTHREADS 256
#define BLOCKS_PER_SM 3
#define NBLOCKS  (148 * BLOCKS_PER_SM)   // persistent grid

struct PS { int base; float w0, w1; };   // w0 = ap*b0, w1 = ap*b1 (column x row weight)

// Per-plane sampling params for one lane (sub-lane s, column p = s>>1).
__device__ __forceinline__ PS plane_setup(float u, float v, int s, int p)
{
    // unnormalize (align_corners=False) + border clamp, reference op order
    float x = ((u + 1.0f) * 512.0f - 1.0f) * 0.5f;
    float y = ((v + 1.0f) * 512.0f - 1.0f) * 0.5f;
    x = fminf(fmaxf(x, 0.0f), 511.0f);
    y = fminf(fmaxf(y, 0.0f), 511.0f);

    float x0f = floorf(x);
    float y0f = floorf(y);
    float wx = x - x0f;
    float wy = y - y0f;
    int x0 = (int)x0f;
    int y0 = (int)y0f;

    int xb = min(x0, 510);
    int yb = min(y0, 510);

    float a1 = (x0 == 511) ? 1.0f : wx;   // weight of column xb+1 (wx==0 there -> exact)
    float ap = p ? a1 : (1.0f - a1);
    float b1 = (y0 == 511) ? 1.0f : wy;

    PS ps;
    ps.w0 = ap * (1.0f - b1);
    ps.w1 = ap * b1;
    ps.base = (((yb << 9) + xb) << 1) + s;  // float4 idx; quad slots [x0h0 x0h1 x1h0 x1h1]
    return ps;
}

__global__ void __launch_bounds__(NTHREADS, BLOCKS_PER_SM)
geo_encoder_kernel(
    const float*  __restrict__ coords,   // [N,3]
    const float4* __restrict__ pxy,
    const float4* __restrict__ pxz,
    const float4* __restrict__ pyz,
    const float*  __restrict__ Wp,       // [8,24]
    const float*  __restrict__ bp,       // [8]
    float*        __restrict__ out,      // [N,8]
    int n)
{
    const int t   = threadIdx.x;
    const int s   = t & 3;       // sub-lane in quad
    const int h   = s & 1;       // rank half (float4 within texel) this lane loads
    const int p   = s >> 1;      // x-column this lane loads; also output group
    const int grp = p;

    // W slice in registers: Wreg[j*12 + q] = W[4*grp+j][plane(q/4)*8 + h*4 + (q%4)]
    float Wreg[48];
    float bias[4];
    const int row0 = 4 * grp;
    #pragma unroll
    for (int j = 0; j < 4; j++) {
        bias[j] = __ldg(bp + row0 + j);
        #pragma unroll
        for (int q = 0; q < 3; q++)
            #pragma unroll
            for (int r = 0; r < 4; r++)
                Wreg[j * 12 + q * 4 + r] = __ldg(Wp + (row0 + j) * 24 + q * 8 + h * 4 + r);
    }

    const int quad   = (blockIdx.x * NTHREADS + t) >> 2;
    const int nquads = (NBLOCKS * NTHREADS) >> 2;
    const int niter  = (n + nquads - 1) / nquads;   // uniform across lanes

    for (int k = 0; k < niter; k++) {
        const int  i   = quad + k * nquads;
        const bool act = (i < n);
        const int  ie  = act ? i : 0;

        float cx = __ldg(coords + 3 * ie + 0);
        float cy = __ldg(coords + 3 * ie + 1);
        float cz = __ldg(coords + 3 * ie + 2);
        cx = fminf(fmaxf(cx, -1.0f), 1.0f);
        cy = fminf(fmaxf(cy, -1.0f), 1.0f);
        cz = fminf(fmaxf(cz, -1.0f), 1.0f);

        const PS a = plane_setup(cx, cy, s, p);
        const PS b = plane_setup(cx, cz, s, p);
        const PS c = plane_setup(cy, cz, s, p);

        // 6 independent gathers, front-batched (max MLP). +1024 float4 = next row.
        const float4 ta = __ldg(pxy + a.base);
        const float4 ba = __ldg(pxy + a.base + 1024);
        const float4 tb = __ldg(pxz + b.base);
        const float4 bb = __ldg(pxz + b.base + 1024);
        const float4 tc = __ldg(pyz + c.base);
        const float4 bc = __ldg(pyz + c.base + 1024);

        // partial features (this lane's column & half), 12 values
        float pf[12];
        pf[0]  = a.w0 * ta.x + a.w1 * ba.x;
        pf[1]  = a.w0 * ta.y + a.w1 * ba.y;
        pf[2]  = a.w0 * ta.z + a.w1 * ba.z;
        pf[3]  = a.w0 * ta.w + a.w1 * ba.w;
        pf[4]  = b.w0 * tb.x + b.w1 * bb.x;
        pf[5]  = b.w0 * tb.y + b.w1 * bb.y;
        pf[6]  = b.w0 * tb.z + b.w1 * bb.z;
        pf[7]  = b.w0 * tb.w + b.w1 * bb.w;
        pf[8]  = c.w0 * tc.x + c.w1 * bc.x;
        pf[9]  = c.w0 * tc.y + c.w1 * bc.y;
        pf[10] = c.w0 * tc.z + c.w1 * bc.z;
        pf[11] = c.w0 * tc.w + c.w1 * bc.w;

        // fused feature-reduce (over x-columns, xor bit1) + register matvec
        float o0 = 0.f, o1 = 0.f, o2 = 0.f, o3 = 0.f;
        #pragma unroll
        for (int q = 0; q < 12; q++) {
            const float g = pf[q] + __shfl_xor_sync(0xffffffffu, pf[q], 2);
            o0 += Wreg[q]      * g;
            o1 += Wreg[12 + q] * g;
            o2 += Wreg[24 + q] * g;
            o3 += Wreg[36 + q] * g;
        }

        // combine rank halves (xor bit0)
        o0 += __shfl_xor_sync(0xffffffffu, o0, 1);
        o1 += __shfl_xor_sync(0xffffffffu, o1, 1);
        o2 += __shfl_xor_sync(0xffffffffu, o2, 1);
        o3 += __shfl_xor_sync(0xffffffffu, o3, 1);

        if (act && h == 0) {
            float4 v;
            v.x = fminf(fmaxf(o0 + bias[0], -10.0f), 10.0f);
            v.y = fminf(fmaxf(o1 + bias[1], -10.0f), 10.0f);
            v.z = fminf(fmaxf(o2 + bias[2], -10.0f), 10.0f);
            v.w = fminf(fmaxf(o3 + bias[3], -10.0f), 10.0f);
            reinterpret_cast<float4*>(out)[(i << 1) + grp] = v;
        }
    }
}

extern "C" void kernel_launch(void* const* d_in, const int* in_sizes, int n_in,
                              void* d_out, int out_size)
{
    const float*  coords = (const float*)d_in[0];
    const float4* pxy    = (const float4*)d_in[1];
    const float4* pxz    = (const float4*)d_in[2];
    const float4* pyz    = (const float4*)d_in[3];
    const float*  Wp     = (const float*)d_in[4];
    const float*  bp     = (const float*)d_in[5];
    float*        out    = (float*)d_out;

    const int n = in_sizes[0] / 3;
    geo_encoder_kernel<<<NBLOCKS, NTHREADS>>>(coords, pxy, pxz, pyz, Wp, bp, out, n);
}